// round 3
// baseline (speedup 1.0000x reference)
#include <cuda_runtime.h>
#include <cuda_bf16.h>

// NeRF volume-rendering composite — persistent single-wave, software-pipelined.
// Inputs (metadata order):
//   0: sigma_vals [N, S] f32   1: rgb_vals [N, S, 3] f32   2: dists [N, S] f32
//   3: z_vals [N, S] f32       4: bg_color [N, 3] f32
// Output: [N, 4] f32 (r, g, b, depth)
//
// One warp per ray, lane l owns samples [4l, 4l+4). Each warp grid-strides
// over rays; the NEXT ray's 6 float4 streaming loads are issued before the
// CURRENT ray's shuffle-scan compute, so memory requests never drain.

#ifndef NSAMP
#define NSAMP 128
#endif

struct RayData { float4 s, d, z, r0, r1, r2; };

__device__ __forceinline__ void load_ray(
    int ray, int lane,
    const float* __restrict__ sigma, const float* __restrict__ dists,
    const float* __restrict__ z_vals, const float* __restrict__ rgb,
    RayData& rd)
{
    const float4* sig4 = reinterpret_cast<const float4*>(sigma  + (size_t)ray * NSAMP);
    const float4* dst4 = reinterpret_cast<const float4*>(dists  + (size_t)ray * NSAMP);
    const float4* zv4  = reinterpret_cast<const float4*>(z_vals + (size_t)ray * NSAMP);
    const float4* rg4  = reinterpret_cast<const float4*>(rgb    + (size_t)ray * NSAMP * 3);
    rd.s  = __ldcs(&sig4[lane]);
    rd.d  = __ldcs(&dst4[lane]);
    rd.z  = __ldcs(&zv4[lane]);
    rd.r0 = __ldcs(&rg4[3 * lane + 0]);   // s0.r s0.g s0.b s1.r
    rd.r1 = __ldcs(&rg4[3 * lane + 1]);   // s1.g s1.b s2.r s2.g
    rd.r2 = __ldcs(&rg4[3 * lane + 2]);   // s2.b s3.r s3.g s3.b
}

__device__ __forceinline__ void compute_store_ray(
    int ray, int lane, const RayData& rd,
    const float* __restrict__ bg, float* __restrict__ out)
{
    const unsigned FULL = 0xFFFFFFFFu;

    // alpha and (1 - alpha + eps)
    float a0, a1, a2, a3, t0, t1, t2, t3, tau;
    tau = fmaxf(rd.s.x, 0.0f) * rd.d.x;  a0 = 1.0f - __expf(-tau);  t0 = 1.0f - a0 + 1e-10f;
    tau = fmaxf(rd.s.y, 0.0f) * rd.d.y;  a1 = 1.0f - __expf(-tau);  t1 = 1.0f - a1 + 1e-10f;
    tau = fmaxf(rd.s.z, 0.0f) * rd.d.z;  a2 = 1.0f - __expf(-tau);  t2 = 1.0f - a2 + 1e-10f;
    tau = fmaxf(rd.s.w, 0.0f) * rd.d.w;  a3 = 1.0f - __expf(-tau);  t3 = 1.0f - a3 + 1e-10f;

    // local inclusive products
    float q0 = t0, q1 = q0 * t1, q2 = q1 * t2, q3 = q2 * t3;

    // multiplicative inclusive warp scan of q3
    float incl = q3;
    #pragma unroll
    for (int off = 1; off < 32; off <<= 1) {
        float v = __shfl_up_sync(FULL, incl, off);
        if (lane >= off) incl *= v;
    }
    float excl = __shfl_up_sync(FULL, incl, 1);
    if (lane == 0) excl = 1.0f;
    float no_hit = __shfl_sync(FULL, incl, 31);

    // weights
    float w0 = a0 * excl;
    float w1 = a1 * (excl * q0);
    float w2 = a2 * (excl * q1);
    float w3 = a3 * (excl * q2);

    float cr = w0 * rd.r0.x + w1 * rd.r0.w + w2 * rd.r1.z + w3 * rd.r2.y;
    float cg = w0 * rd.r0.y + w1 * rd.r1.x + w2 * rd.r1.w + w3 * rd.r2.z;
    float cb = w0 * rd.r0.z + w1 * rd.r1.y + w2 * rd.r2.x + w3 * rd.r2.w;
    float dep = w0 * rd.z.x + w1 * rd.z.y + w2 * rd.z.z + w3 * rd.z.w;

    // butterfly reductions
    #pragma unroll
    for (int off = 16; off > 0; off >>= 1) {
        cr  += __shfl_xor_sync(FULL, cr,  off);
        cg  += __shfl_xor_sync(FULL, cg,  off);
        cb  += __shfl_xor_sync(FULL, cb,  off);
        dep += __shfl_xor_sync(FULL, dep, off);
    }

    if (lane == 0) {
        const float* bgp = bg + (size_t)ray * 3;
        float4 o;
        o.x = cr + no_hit * __ldg(&bgp[0]);
        o.y = cg + no_hit * __ldg(&bgp[1]);
        o.z = cb + no_hit * __ldg(&bgp[2]);
        o.w = dep;
        __stcs(&reinterpret_cast<float4*>(out)[ray], o);
    }
}

__global__ __launch_bounds__(256, 4) void raymarch_kernel(
    const float* __restrict__ sigma,
    const float* __restrict__ rgb,
    const float* __restrict__ dists,
    const float* __restrict__ z_vals,
    const float* __restrict__ bg,
    float* __restrict__ out,
    int n_rays)
{
    const int wib  = threadIdx.x >> 5;
    const int lane = threadIdx.x & 31;
    const int warps_per_block = blockDim.x >> 5;
    const int nwarps = gridDim.x * warps_per_block;

    int ray = blockIdx.x * warps_per_block + wib;
    if (ray >= n_rays) return;

    RayData cur;
    load_ray(ray, lane, sigma, dists, z_vals, rgb, cur);

    for (;;) {
        int next = ray + nwarps;
        bool have_next = (next < n_rays);

        RayData nxt;
        if (have_next) {
            // prefetch next ray BEFORE current ray's compute phase
            load_ray(next, lane, sigma, dists, z_vals, rgb, nxt);
        }

        compute_store_ray(ray, lane, cur, bg, out);

        if (!have_next) break;
        cur = nxt;
        ray = next;
    }
}

extern "C" void kernel_launch(void* const* d_in, const int* in_sizes, int n_in,
                              void* d_out, int out_size) {
    const float* sigma  = (const float*)d_in[0];
    const float* rgb    = (const float*)d_in[1];
    const float* dists  = (const float*)d_in[2];
    const float* z_vals = (const float*)d_in[3];
    const float* bg     = (const float*)d_in[4];
    float* out = (float*)d_out;

    int n_rays = in_sizes[4] / 3;   // bg_color is [N, 3]

    // Persistent single wave: 148 SMs x 4 blocks x 256 threads (32 warps/SM).
    int blocks = 592;
    int threads = 256;
    int total_warps = blocks * (threads / 32);
    if (total_warps > n_rays) {   // tiny-input fallback
        blocks = (n_rays * 32 + threads - 1) / threads;
        if (blocks < 1) blocks = 1;
    }
    raymarch_kernel<<<blocks, threads>>>(sigma, rgb, dists, z_vals, bg, out, n_rays);
}